// round 11
// baseline (speedup 1.0000x reference)
#include <cuda_runtime.h>
#include <cuda_fp16.h>
#include <math.h>
#include <cstdint>

#define B_ 8
#define N_ 1024
#define HID_ 1024
#define HEADS_ 16
#define HD_ 64
#define GDIM_ 128

// Scratch (allocation-free rule: __device__ globals)
__device__ float g_Q[B_ * N_ * HID_];
__device__ float g_K[B_ * N_ * HID_];
__device__ float g_V[B_ * N_ * HID_];
__device__ float g_O[B_ * N_ * HID_];
__device__ float g_addk[B_ * HID_];

__device__ __forceinline__ uint32_t smem_to_u32(const void* p) {
    uint32_t a;
    asm("{ .reg .u64 t; cvta.to.shared.u64 t, %1; cvt.u32.u64 %0, t; }"
        : "=r"(a) : "l"(p));
    return a;
}
__device__ __forceinline__ uint32_t h2(float lo, float hi) {
    __half2 h = __floats2half2_rn(lo, hi);
    return *reinterpret_cast<uint32_t*>(&h);
}
__device__ __forceinline__ void mma_f16(float c[4], const uint32_t a[4],
                                        const uint32_t b[2]) {
    asm volatile(
        "mma.sync.aligned.m16n8k16.row.col.f32.f16.f16.f32 "
        "{%0,%1,%2,%3}, {%4,%5,%6,%7}, {%8,%9}, {%0,%1,%2,%3};"
        : "+f"(c[0]), "+f"(c[1]), "+f"(c[2]), "+f"(c[3])
        : "r"(a[0]), "r"(a[1]), "r"(a[2]), "r"(a[3]), "r"(b[0]), "r"(b[1]));
}
#define STS32(addr, v) \
    asm volatile("st.shared.b32 [%0], %1;" :: "r"(addr), "r"(v) : "memory")
#define LDS128(addr, r0, r1, r2, r3) \
    asm volatile("ld.shared.v4.b32 {%0,%1,%2,%3}, [%4];" \
        : "=r"(r0), "=r"(r1), "=r"(r2), "=r"(r3) : "r"(addr))
#define LDS64(addr, r0, r1) \
    asm volatile("ld.shared.v2.b32 {%0,%1}, [%2];" \
        : "=r"(r0), "=r"(r1) : "r"(addr))

// Rotate float4 left by r (out[p] = in[(p+r)&3]), branch-free per-thread.
__device__ __forceinline__ float4 rot4(float4 v, int r) {
    if (r & 1) { float t = v.x; v.x = v.y; v.y = v.z; v.z = v.w; v.w = t; }
    if (r & 2) { float t = v.x; v.x = v.z; v.z = t; t = v.y; v.y = v.w; v.w = t; }
    return v;
}

// FFMA-pipe exp (deg-5 exp2 poly, rel err ~2e-6). No MUFU.
__device__ __forceinline__ float fexp(float s) {
    float x = s * 1.4426950408889634f;
    int n = __float2int_rn(x);
    float f = x - (float)n;
    float p = 1.3333558146e-3f;
    p = fmaf(p, f, 9.6181291076e-3f);
    p = fmaf(p, f, 5.5504108664e-2f);
    p = fmaf(p, f, 2.4022650696e-1f);
    p = fmaf(p, f, 6.9314718056e-1f);
    p = fmaf(p, f, 1.0f);
    n = max(-126, min(127, n));
    float sc = __int_as_float((uint32_t)(n + 127) << 23);
    return p * sc;
}

// ===========================================================================
// Prep: addk[b][c] = elu(gc[b] @ Wgk + bgk)[c] + ct_key_emb[ct[b]][c]
// ===========================================================================
__global__ void prep_addk_kernel(const int* __restrict__ ct,
                                 const float* __restrict__ gc,
                                 const float* __restrict__ Wgk,
                                 const float* __restrict__ bgk,
                                 const float* __restrict__ ct_key_emb) {
    int b = blockIdx.x;
    int tid = threadIdx.x;
    __shared__ float g[GDIM_];
    g[tid] = gc[b * GDIM_ + tid];
    __syncthreads();
    int ctb = ct[b];
    for (int c = tid; c < HID_; c += GDIM_) {
        float s = bgk[c];
        #pragma unroll 8
        for (int i = 0; i < GDIM_; i++) s = fmaf(g[i], Wgk[i * HID_ + c], s);
        float e = (s > 0.f) ? s : (expf(s) - 1.f);
        g_addk[b * HID_ + c] = e + ct_key_emb[ctb * HID_ + c];
    }
}

// ===========================================================================
// fp16 m16n8k16 GEMM: C[8192,1024] = A @ W + bias (+addk). BK=32.
// CTA 128x128, 8 warps (wm=w>>2, wn=w&3), warp tile 64x32.
// smem: A[2][8KB] @0, B[2][8KB] @16384. Total 32KB. Conflict-free STS.
// ===========================================================================
#define GEMM_SMEM 32768

__global__ __launch_bounds__(256) void gemm3_mma_kernel(
    const float* __restrict__ A,
    const float* __restrict__ W0, const float* __restrict__ W1,
    const float* __restrict__ W2,
    const float* __restrict__ bi0, const float* __restrict__ bi1,
    const float* __restrict__ bi2,
    const float* __restrict__ addk,
    float* __restrict__ C0, float* __restrict__ C1, float* __restrict__ C2) {
    extern __shared__ float sm[];
    uint32_t Abase = smem_to_u32(sm);
    uint32_t Bbase = Abase + 16384;

    int z = blockIdx.z;
    const float* W = (z == 0) ? W0 : ((z == 1) ? W1 : W2);
    const float* bias = (z == 0) ? bi0 : ((z == 1) ? bi1 : bi2);
    float* C = (z == 0) ? C0 : ((z == 1) ? C1 : C2);
    const float* ak = (z == 1) ? addk : nullptr;

    int tid = threadIdx.x;
    int lane = tid & 31, w = tid >> 5;
    int wm = w >> 2, wn = w & 3;
    int m0 = blockIdx.y * 128, n0 = blockIdx.x * 128;

    int l0 = lane & 1, l1 = (lane >> 1) & 1, l2 = (lane >> 2) & 1;
    int l34 = lane >> 3, l3 = l34 & 1, l4 = (l34 >> 1) & 1;

    float c[4][4][4];
    #pragma unroll
    for (int i = 0; i < 4; i++)
        #pragma unroll
        for (int j = 0; j < 4; j++)
            #pragma unroll
            for (int r = 0; r < 4; r++) c[i][j][r] = 0.f;

    float4 aR[4], b0R[2], b1R[2];
    int b_nq = l34 + 4 * w;  // B n-quad (fixed per thread)

    #define LDG_CHUNK(k0)                                                      \
        do {                                                                   \
            _Pragma("unroll")                                                  \
            for (int it = 0; it < 4; it++) {                                   \
                int m = 16 * w + l0 + 2 * (it >> 1) + 4 * l2 + 8 * l1;         \
                int q = l34 + 4 * (it & 1);                                    \
                aR[it] = *(const float4*)(A + (size_t)(m0 + m) * 1024 +        \
                                          (k0) + q * 4);                       \
            }                                                                  \
            _Pragma("unroll")                                                  \
            for (int itb = 0; itb < 2; itb++) {                                \
                int kb = 2 * ((lane & 7) + 8 * itb);                           \
                const float* wp = W + (size_t)((k0) + kb) * 1024 + n0 +        \
                                  b_nq * 4;                                    \
                b0R[itb] = *(const float4*)wp;                                 \
                b1R[itb] = *(const float4*)(wp + 1024);                        \
            }                                                                  \
        } while (0)

    #define STS_CHUNK(buf)                                                     \
        do {                                                                   \
            uint32_t Ab = Abase + (buf) * 8192;                                \
            uint32_t Bb = Bbase + (buf) * 8192;                                \
            _Pragma("unroll")                                                  \
            for (int it = 0; it < 4; it++) {                                   \
                int r = l0 | ((it >> 1) << 1) | (l2 << 2) | (l1 << 3);         \
                uint32_t tile = (uint32_t)((it & 1) * 8 + w);                  \
                uint32_t reg = (uint32_t)(l1 | (l4 << 1));                     \
                uint32_t lane_hi = (uint32_t)(((r & 7) << 2) | (l3 << 1));     \
                uint32_t ba = Ab + tile * 512 + reg * 4;                       \
                uint32_t p0 = h2(aR[it].x, aR[it].y);                          \
                uint32_t p1 = h2(aR[it].z, aR[it].w);                          \
                STS32(ba + ((lane_hi | (uint32_t)l2) << 4), l2 ? p1 : p0);     \
                STS32(ba + ((lane_hi | (uint32_t)(1 - l2)) << 4), l2 ? p0 : p1); \
            }                                                                  \
            _Pragma("unroll")                                                  \
            for (int itb = 0; itb < 2; itb++) {                                \
                uint32_t tile = (uint32_t)(itb * 16 + l4 + 2 * w);             \
                int rot = l34 & 3;                                             \
                float4 c0 = rot4(b0R[itb], rot);                               \
                float4 c1 = rot4(b1R[itb], rot);                               \
                uint32_t bb = Bb + tile * 256 + (uint32_t)l3 * 128 +           \
                              (uint32_t)(lane & 3) * 8 + (uint32_t)l2 * 4;     \
                STS32(bb + (uint32_t)(((rot + 0) & 3) << 5), h2(c0.x, c1.x));  \
                STS32(bb + (uint32_t)(((rot + 1) & 3) << 5), h2(c0.y, c1.y));  \
                STS32(bb + (uint32_t)(((rot + 2) & 3) << 5), h2(c0.z, c1.z));  \
                STS32(bb + (uint32_t)(((rot + 3) & 3) << 5), h2(c0.w, c1.w));  \
            }                                                                  \
        } while (0)

    LDG_CHUNK(0);
    STS_CHUNK(0);
    __syncthreads();

    for (int ch = 0; ch < 32; ch++) {
        int buf = ch & 1;
        if (ch < 31) LDG_CHUNK((ch + 1) * 32);

        uint32_t Ab = Abase + buf * 8192;
        uint32_t Bb = Bbase + buf * 8192;
        #pragma unroll
        for (int ks = 0; ks < 2; ks++) {
            uint32_t af[4][4], bf[4][2];
            #pragma unroll
            for (int i = 0; i < 4; i++)
                LDS128(Ab + (uint32_t)(ks * 8 + wm * 4 + i) * 512 +
                           (uint32_t)lane * 16,
                       af[i][0], af[i][1], af[i][2], af[i][3]);
            #pragma unroll
            for (int j = 0; j < 4; j++)
                LDS64(Bb + (uint32_t)(ks * 16 + wn * 4 + j) * 256 +
                          (uint32_t)lane * 8,
                      bf[j][0], bf[j][1]);
            #pragma unroll
            for (int i = 0; i < 4; i++)
                #pragma unroll
                for (int j = 0; j < 4; j++) mma_f16(c[i][j], af[i], bf[j]);
        }

        if (ch < 31) STS_CHUNK(buf ^ 1);
        __syncthreads();
    }

    int b = m0 >> 10;
    #pragma unroll
    for (int i = 0; i < 4; i++) {
        int row = m0 + wm * 64 + i * 16 + (lane >> 2);
        #pragma unroll
        for (int j = 0; j < 4; j++) {
            int col = n0 + wn * 32 + j * 8 + (lane & 3) * 2;
            float bb0 = bias[col], bb1 = bias[col + 1];
            if (ak) {
                bb0 += ak[b * HID_ + col];
                bb1 += ak[b * HID_ + col + 1];
            }
            *(float2*)(C + (size_t)row * 1024 + col) =
                make_float2(c[i][j][0] + bb0, c[i][j][1] + bb1);
            *(float2*)(C + (size_t)(row + 8) * 1024 + col) =
                make_float2(c[i][j][2] + bb0, c[i][j][3] + bb1);
        }
    }
}

// ===========================================================================
// fp16 flash attention. P fragments pass register-direct from S accumulators
// to the PV mma (no P smem). K/V double-buffered, conflict-free half2 STS.
// smem: K[2][8KB] @0, V[2][8KB] @16384, mask[2][64]f @32768.
// ===========================================================================
#define ATTN_SMEM (32768 + 512)

__global__ __launch_bounds__(256) void attn_mma_kernel(
    const float* __restrict__ Q, const float* __restrict__ K,
    const float* __restrict__ V, const unsigned char* __restrict__ mask,
    float* __restrict__ O) {
    extern __shared__ float sm[];
    uint32_t base = smem_to_u32(sm);
    uint32_t Kf = base;
    uint32_t Vf = base + 16384;
    float* Msf = sm + 32768 / 4;

    int tid = threadIdx.x;
    int lane = tid & 31, w = tid >> 5;
    int l0 = lane & 1, l1 = (lane >> 1) & 1, l2 = (lane >> 2) & 1;
    int l34 = lane >> 3, l3 = l34 & 1, l4 = (l34 >> 1) & 1;
    int r = lane >> 2, cl = lane & 3;
    int qt = blockIdx.x, h = blockIdx.y, b = blockIdx.z;

    const float* Qg = Q + ((size_t)(b * N_ + qt * 128) * HID_ + h * HD_);
    const float* Kg = K + ((size_t)b * N_ * HID_ + h * HD_);
    const float* Vg = V + ((size_t)b * N_ * HID_ + h * HD_);

    // Q fragments (half2), scaled by 1/8: warp w owns rows 16w..16w+15
    uint32_t qh[4][4];
    {
        const float sc = 0.125f;
        int m = 16 * w + r;
        #pragma unroll
        for (int ks = 0; ks < 4; ks++) {
            float2 v0 = *(const float2*)(Qg + (size_t)m * HID_ + 16 * ks + 2 * cl);
            float2 v1 = *(const float2*)(Qg + (size_t)(m + 8) * HID_ + 16 * ks + 2 * cl);
            float2 v2 = *(const float2*)(Qg + (size_t)m * HID_ + 16 * ks + 8 + 2 * cl);
            float2 v3 = *(const float2*)(Qg + (size_t)(m + 8) * HID_ + 16 * ks + 8 + 2 * cl);
            qh[ks][0] = h2(v0.x * sc, v0.y * sc);
            qh[ks][1] = h2(v1.x * sc, v1.y * sc);
            qh[ks][2] = h2(v2.x * sc, v2.y * sc);
            qh[ks][3] = h2(v3.x * sc, v3.y * sc);
        }
    }

    // LDG slot assignments
    int kvK = 8 * w + (lane & 7);            // K row within tile
    int vkap[2], vdq = l34 + 4 * (w >> 1);   // V: kappa per itv, d-quad
    vkap[0] = (lane & 7) + 16 * (w & 1);
    vkap[1] = (lane & 7) + 8 + 16 * (w & 1);

    float4 kR[4], vA[2], vB[2];

    #define AT_LDG(t)                                                          \
        do {                                                                   \
            const float* kp = Kg + (size_t)((t) * 64 + kvK) * HID_;            \
            _Pragma("unroll")                                                  \
            for (int it = 0; it < 4; it++)                                     \
                kR[it] = *(const float4*)(kp + 4 * l34 + 16 * it);             \
            _Pragma("unroll")                                                  \
            for (int itv = 0; itv < 2; itv++) {                                \
                const float* vp = Vg + (size_t)((t) * 64 + 2 * vkap[itv]) *    \
                                  HID_ + 4 * vdq;                              \
                vA[itv] = *(const float4*)vp;                                  \
                vB[itv] = *(const float4*)(vp + HID_);                         \
            }                                                                  \
        } while (0)

    #define AT_STS(buf, t)                                                     \
        do {                                                                   \
            uint32_t Kb = Kf + (buf) * 8192;                                   \
            uint32_t Vb = Vf + (buf) * 8192;                                   \
            _Pragma("unroll")                                                  \
            for (int it = 0; it < 4; it++) {                                   \
                uint32_t tile = (uint32_t)(it * 8 + w);                        \
                uint32_t lane_hi = (uint32_t)(((lane & 7) << 2) | (l3 << 1));  \
                uint32_t ba = Kb + tile * 256 + (uint32_t)l4 * 4;              \
                uint32_t p0 = h2(kR[it].x, kR[it].y);                          \
                uint32_t p1 = h2(kR[it].z, kR[it].w);                          \
                STS32(ba + ((lane_hi | (uint32_t)l2) << 3), l2 ? p1 : p0);     \
                STS32(ba + ((lane_hi | (uint32_t)(1 - l2)) << 3), l2 ? p0 : p1); \
            }                                                                  \
            _Pragma("unroll")                                                  \
            for (int itv = 0; itv < 2; itv++) {                                \
                uint32_t ks2 = (uint32_t)(itv + 2 * (w & 1));                  \
                uint32_t tile = ks2 * 8 + (uint32_t)(l4 + 2 * (w >> 1));       \
                int rot = l34 & 3;                                             \
                float4 c0 = rot4(vA[itv], rot);                                \
                float4 c1 = rot4(vB[itv], rot);                                \
                uint32_t bb = Vb + tile * 256 + (uint32_t)l3 * 128 +           \
                              (uint32_t)(lane & 3) * 8 + (uint32_t)l2 * 4;     \
                STS32(bb + (uint32_t)(((rot + 0) & 3) << 5), h2(c0.x, c1.x));  \
                STS32(bb + (uint32_t)(((rot + 1) & 3) << 5), h2(c0.y, c1.y));  \
                STS32(bb + (uint32_t)(((rot + 2) & 3) << 5), h2(c0.z, c1.z));  \
                STS32(bb + (uint32_t)(((rot + 3) & 3) << 5), h2(c0.w, c1.w));  \
            }                                                                  \
            if (tid < 64)                                                      \
                Msf[(buf) * 64 + tid] =                                        \
                    mask[b * N_ + (t) * 64 + tid] ? 0.f : 1.f;                 \
        } while (0)

    float oacc[8][4];
    #pragma unroll
    for (int nf = 0; nf < 8; nf++)
        #pragma unroll
        for (int x = 0; x < 4; x++) oacc[nf][x] = 0.f;
    float sum0 = 0.f, sum1 = 0.f;

    AT_LDG(0);
    AT_STS(0, 0);
    __syncthreads();

    for (int t = 0; t < 16; t++) {
        int buf = t & 1;
        if (t < 15) AT_LDG(t + 1);

        uint32_t Kb = Kf + buf * 8192;
        uint32_t Vb = Vf + buf * 8192;

        // S = Q K^T
        float sacc[8][4];
        #pragma unroll
        for (int nf = 0; nf < 8; nf++)
            #pragma unroll
            for (int x = 0; x < 4; x++) sacc[nf][x] = 0.f;
        #pragma unroll
        for (int ks = 0; ks < 4; ks++) {
            #pragma unroll
            for (int nf = 0; nf < 8; nf++) {
                uint32_t bf[2];
                LDS64(Kb + (uint32_t)(ks * 8 + nf) * 256 + (uint32_t)lane * 8,
                      bf[0], bf[1]);
                mma_f16(sacc[nf], qh[ks], bf);
            }
        }

        // exp + mask; P half2 fragments stay in registers
        uint32_t ph[8][2];
        const float* Mb = Msf + buf * 64;
        #pragma unroll
        for (int nf = 0; nf < 8; nf++) {
            float mm0 = Mb[nf * 8 + 2 * cl];
            float mm1 = Mb[nf * 8 + 2 * cl + 1];
            float p0 = fexp(sacc[nf][0]) * mm0;
            float p1 = fexp(sacc[nf][1]) * mm1;
            float p2 = fexp(sacc[nf][2]) * mm0;
            float p3 = fexp(sacc[nf][3]) * mm1;
            sum0 += p0 + p1;
            sum1 += p2 + p3;
            ph[nf][0] = h2(p0, p1);
            ph[nf][1] = h2(p2, p3);
        }

        // O += P V (A fragments direct from registers)
        #pragma unroll
        for (int ks2 = 0; ks2 < 4; ks2++) {
            uint32_t a[4] = {ph[2 * ks2][0], ph[2 * ks2][1],
                             ph[2 * ks2 + 1][0], ph[2 * ks2 + 1][1]};
            #pragma unroll
            for (int nf = 0; nf < 8; nf++) {
                uint32_t vf[2];
                LDS64(Vb + (uint32_t)(ks2 * 8 + nf) * 256 + (uint32_t)lane * 8,
                      vf[0], vf[1]);
                mma_f16(oacc[nf], a, vf);
            }
        }

        if (t < 15) {
            __syncthreads();
            AT_STS(buf ^ 1, t + 1);
            __syncthreads();
        }
    }

    sum0 += __shfl_xor_sync(0xffffffffu, sum0, 1);
    sum0 += __shfl_xor_sync(0xffffffffu, sum0, 2);
    sum1 += __shfl_xor_sync(0xffffffffu, sum1, 1);
    sum1 += __shfl_xor_sync(0xffffffffu, sum1, 2);
    float inv0 = 1.f / sum0, inv1 = 1.f / sum1;

    int row0 = b * N_ + qt * 128 + 16 * w + r;
    #pragma unroll
    for (int nf = 0; nf < 8; nf++) {
        int col = h * HD_ + nf * 8 + 2 * cl;
        *(float2*)(O + (size_t)row0 * HID_ + col) =
            make_float2(oacc[nf][0] * inv0, oacc[nf][1] * inv0);
        *(float2*)(O + (size_t)(row0 + 8) * HID_ + col) =
            make_float2(oacc[nf][2] * inv1, oacc[nf][3] * inv1);
    }
}

// ===========================================================================
extern "C" void kernel_launch(void* const* d_in, const int* in_sizes, int n_in,
                              void* d_out, int out_size) {
    const float* x = (const float*)d_in[0];
    const int* ct = (const int*)d_in[1];
    const float* gc = (const float*)d_in[2];
    const unsigned char* mask = (const unsigned char*)d_in[3];
    const float* Wq = (const float*)d_in[4];
    const float* bq = (const float*)d_in[5];
    const float* Wk = (const float*)d_in[6];
    const float* bk = (const float*)d_in[7];
    const float* Wv = (const float*)d_in[8];
    const float* bv = (const float*)d_in[9];
    const float* Wo = (const float*)d_in[10];
    const float* bo = (const float*)d_in[11];
    // d_in[12] ct_bias_emb, d_in[14..17] Wg1/bg1/Wg2/bg2 cancel in softmax
    const float* ct_key = (const float*)d_in[13];
    const float* Wgk = (const float*)d_in[18];
    const float* bgk = (const float*)d_in[19];

    float *Qb, *Kb, *Vb, *Ob, *addk;
    cudaGetSymbolAddress((void**)&Qb, g_Q);
    cudaGetSymbolAddress((void**)&Kb, g_K);
    cudaGetSymbolAddress((void**)&Vb, g_V);
    cudaGetSymbolAddress((void**)&Ob, g_O);
    cudaGetSymbolAddress((void**)&addk, g_addk);

    cudaFuncSetAttribute(gemm3_mma_kernel, cudaFuncAttributeMaxDynamicSharedMemorySize,
                         GEMM_SMEM);
    cudaFuncSetAttribute(attn_mma_kernel, cudaFuncAttributeMaxDynamicSharedMemorySize,
                         ATTN_SMEM);

    prep_addk_kernel<<<B_, GDIM_>>>(ct, gc, Wgk, bgk, ct_key);

    // Fused Q/K/V projections: z selects weight/bias/output; addk applies to K.
    dim3 qkvgrid(HID_ / 128, (B_ * N_) / 128, 3);  // (8, 64, 3)
    gemm3_mma_kernel<<<qkvgrid, 256, GEMM_SMEM>>>(
        x, Wq, Wk, Wv, bq, bk, bv, addk, Qb, Kb, Vb);

    dim3 agrid(N_ / 128, HEADS_, B_);  // (8, 16, 8)
    attn_mma_kernel<<<agrid, 256, ATTN_SMEM>>>(Qb, Kb, Vb, mask, Ob);

    dim3 ogrid(HID_ / 128, (B_ * N_) / 128, 1);
    gemm3_mma_kernel<<<ogrid, 256, GEMM_SMEM>>>(
        Ob, Wo, Wo, Wo, bo, bo, bo, nullptr, (float*)d_out, nullptr, nullptr);
}

// round 12
// speedup vs baseline: 2.0144x; 2.0144x over previous
#include <cuda_runtime.h>
#include <cuda_fp16.h>
#include <math.h>
#include <cstdint>

#define B_ 8
#define N_ 1024
#define HID_ 1024
#define HEADS_ 16
#define HD_ 64
#define GDIM_ 128

// Scratch (allocation-free rule: __device__ globals)
__device__ float g_Q[B_ * N_ * HID_];
__device__ float g_K[B_ * N_ * HID_];
__device__ float g_V[B_ * N_ * HID_];
__device__ __half g_Oh[B_ * N_ * HID_];
__device__ __half g_xh[B_ * N_ * HID_];
__device__ __half g_Wqh[HID_ * HID_];
__device__ __half g_Wkh[HID_ * HID_];
__device__ __half g_Wvh[HID_ * HID_];
__device__ __half g_Woh[HID_ * HID_];
__device__ float g_addk[B_ * HID_];

__device__ __forceinline__ uint32_t smem_to_u32(const void* p) {
    uint32_t a;
    asm("{ .reg .u64 t; cvta.to.shared.u64 t, %1; cvt.u32.u64 %0, t; }"
        : "=r"(a) : "l"(p));
    return a;
}
__device__ __forceinline__ uint32_t h2(float lo, float hi) {
    __half2 h = __floats2half2_rn(lo, hi);
    return *reinterpret_cast<uint32_t*>(&h);
}
__device__ __forceinline__ void mma_f16(float c[4], const uint32_t a[4],
                                        const uint32_t b[2]) {
    asm volatile(
        "mma.sync.aligned.m16n8k16.row.col.f32.f16.f16.f32 "
        "{%0,%1,%2,%3}, {%4,%5,%6,%7}, {%8,%9}, {%0,%1,%2,%3};"
        : "+f"(c[0]), "+f"(c[1]), "+f"(c[2]), "+f"(c[3])
        : "r"(a[0]), "r"(a[1]), "r"(a[2]), "r"(a[3]), "r"(b[0]), "r"(b[1]));
}
#define STS32(addr, v) \
    asm volatile("st.shared.b32 [%0], %1;" :: "r"(addr), "r"(v) : "memory")
#define LDS64(addr, r0, r1) \
    asm volatile("ld.shared.v2.b32 {%0,%1}, [%2];" \
        : "=r"(r0), "=r"(r1) : "r"(addr))
#define LDSM_X4(r0, r1, r2, r3, addr) \
    asm volatile("ldmatrix.sync.aligned.m8n8.x4.shared.b16 {%0,%1,%2,%3}, [%4];" \
        : "=r"(r0), "=r"(r1), "=r"(r2), "=r"(r3) : "r"(addr))
#define LDSM_X4T(r0, r1, r2, r3, addr) \
    asm volatile("ldmatrix.sync.aligned.m8n8.x4.trans.shared.b16 {%0,%1,%2,%3}, [%4];" \
        : "=r"(r0), "=r"(r1), "=r"(r2), "=r"(r3) : "r"(addr))
#define CP_ASYNC16(dst, src) \
    asm volatile("cp.async.cg.shared.global [%0], [%1], 16;" \
        :: "r"(dst), "l"(src) : "memory")
#define CP_COMMIT() asm volatile("cp.async.commit_group;" ::: "memory")
#define CP_WAIT2() asm volatile("cp.async.wait_group 2;" ::: "memory")

// Rotate float4 left by r (out[p] = in[(p+r)&3]), branch-free per-thread.
__device__ __forceinline__ float4 rot4(float4 v, int r) {
    if (r & 1) { float t = v.x; v.x = v.y; v.y = v.z; v.z = v.w; v.w = t; }
    if (r & 2) { float t = v.x; v.x = v.z; v.z = t; t = v.y; v.y = v.w; v.w = t; }
    return v;
}

// FFMA-pipe exp (deg-5 exp2 poly, rel err ~2e-6). No MUFU.
__device__ __forceinline__ float fexp(float s) {
    float x = s * 1.4426950408889634f;
    int n = __float2int_rn(x);
    float f = x - (float)n;
    float p = 1.3333558146e-3f;
    p = fmaf(p, f, 9.6181291076e-3f);
    p = fmaf(p, f, 5.5504108664e-2f);
    p = fmaf(p, f, 2.4022650696e-1f);
    p = fmaf(p, f, 6.9314718056e-1f);
    p = fmaf(p, f, 1.0f);
    n = max(-126, min(127, n));
    float sc = __int_as_float((uint32_t)(n + 127) << 23);
    return p * sc;
}

// ===========================================================================
// fp32 -> fp16 conversion (grid-stride over float4)
// ===========================================================================
__global__ void f2h_kernel(const float* __restrict__ s, __half* __restrict__ d,
                           int n4) {
    int i = blockIdx.x * blockDim.x + threadIdx.x;
    if (i < n4) {
        float4 v = ((const float4*)s)[i];
        uint2 o;
        o.x = h2(v.x, v.y);
        o.y = h2(v.z, v.w);
        ((uint2*)d)[i] = o;
    }
}

// ===========================================================================
// Prep: addk[b][c] = elu(gc[b] @ Wgk + bgk)[c] + ct_key_emb[ct[b]][c]
// ===========================================================================
__global__ void prep_addk_kernel(const int* __restrict__ ct,
                                 const float* __restrict__ gc,
                                 const float* __restrict__ Wgk,
                                 const float* __restrict__ bgk,
                                 const float* __restrict__ ct_key_emb) {
    int b = blockIdx.x;
    int tid = threadIdx.x;
    __shared__ float g[GDIM_];
    g[tid] = gc[b * GDIM_ + tid];
    __syncthreads();
    int ctb = ct[b];
    for (int c = tid; c < HID_; c += GDIM_) {
        float s = bgk[c];
        #pragma unroll 8
        for (int i = 0; i < GDIM_; i++) s = fmaf(g[i], Wgk[i * HID_ + c], s);
        float e = (s > 0.f) ? s : (expf(s) - 1.f);
        g_addk[b * HID_ + c] = e + ct_key_emb[ctb * HID_ + c];
    }
}

// ===========================================================================
// fp16 cp.async + ldmatrix GEMM: C[8192,1024] = A @ W + bias (+addk).
// CTA 128x128, BK=32, 4 stages (16KB each, 64KB total), 2 CTAs/SM.
// A smem: 128 rows x 64B, swizzle chunk c^((row>>1)&3).
// B smem: 32 k-rows x 256B, swizzle chunk c^(k&7).
// ===========================================================================
#define GEMM_SMEM 65536

__global__ __launch_bounds__(256, 2) void gemm3h_kernel(
    const __half* __restrict__ A,
    const __half* __restrict__ W0, const __half* __restrict__ W1,
    const __half* __restrict__ W2,
    const float* __restrict__ bi0, const float* __restrict__ bi1,
    const float* __restrict__ bi2,
    const float* __restrict__ addk,
    float* __restrict__ C0, float* __restrict__ C1, float* __restrict__ C2) {
    extern __shared__ float sm[];
    uint32_t sbase = smem_to_u32(sm);

    int z = blockIdx.z;
    const __half* W = (z == 0) ? W0 : ((z == 1) ? W1 : W2);
    const float* bias = (z == 0) ? bi0 : ((z == 1) ? bi1 : bi2);
    float* C = (z == 0) ? C0 : ((z == 1) ? C1 : C2);
    const float* ak = (z == 1) ? addk : nullptr;

    int tid = threadIdx.x;
    int lane = tid & 31, w = tid >> 5;
    int wm = w >> 2, wn = w & 3;
    int m0 = blockIdx.y * 128, n0 = blockIdx.x * 128;

    // copy-slot precompute (2 A chunks + 2 B chunks per thread per stage)
    int arow0 = tid >> 2, ac = tid & 3;            // + 64 for slot 1
    uint32_t asm0 = (uint32_t)(arow0 * 64 + ((ac ^ ((arow0 >> 1) & 3)) << 4));
    int arow1 = arow0 + 64;
    uint32_t asm1 = (uint32_t)(arow1 * 64 + ((ac ^ ((arow1 >> 1) & 3)) << 4));
    int bkr0 = tid >> 4, bc = tid & 15;            // + 16 for slot 1
    uint32_t bsm0 = (uint32_t)(bkr0 * 256 + ((bc ^ (bkr0 & 7)) << 4) + 8192);
    int bkr1 = bkr0 + 16;
    uint32_t bsm1 = (uint32_t)(bkr1 * 256 + ((bc ^ (bkr1 & 7)) << 4) + 8192);

    #define ISSUE(stage, k0)                                                   \
        do {                                                                   \
            uint32_t sb = sbase + (uint32_t)(stage) * 16384;                   \
            CP_ASYNC16(sb + asm0,                                              \
                       A + (size_t)(m0 + arow0) * 1024 + (k0) + ac * 8);       \
            CP_ASYNC16(sb + asm1,                                              \
                       A + (size_t)(m0 + arow1) * 1024 + (k0) + ac * 8);       \
            CP_ASYNC16(sb + bsm0,                                              \
                       W + (size_t)((k0) + bkr0) * 1024 + n0 + bc * 8);        \
            CP_ASYNC16(sb + bsm1,                                              \
                       W + (size_t)((k0) + bkr1) * 1024 + n0 + bc * 8);        \
            CP_COMMIT();                                                       \
        } while (0)

    // ldmatrix address precompute
    int a_row = wm * 64 + (lane & 15);          // + 16*i
    int a_swz = ((lane & 15) >> 1) & 3;         // (row>>1)&3 since base%16==0
    int b_kr = (lane & 7) + 8 * ((lane >> 3) & 1);  // + 16*ks
    int b_chi = lane >> 4;

    float c[4][4][4];
    #pragma unroll
    for (int i = 0; i < 4; i++)
        #pragma unroll
        for (int j = 0; j < 4; j++)
            #pragma unroll
            for (int r = 0; r < 4; r++) c[i][j][r] = 0.f;

    ISSUE(0, 0);
    ISSUE(1, 32);
    ISSUE(2, 64);

    for (int ch = 0; ch < 32; ch++) {
        CP_WAIT2();
        __syncthreads();
        uint32_t sb = sbase + (uint32_t)(ch & 3) * 16384;

        #pragma unroll
        for (int ks = 0; ks < 2; ks++) {
            uint32_t af[4][4], bf[4][2];
            #pragma unroll
            for (int i = 0; i < 4; i++) {
                int row = a_row + 16 * i;
                int cc = 2 * ks + b_chi;
                uint32_t addr = sb + (uint32_t)(row * 64 + ((cc ^ a_swz) << 4));
                LDSM_X4(af[i][0], af[i][1], af[i][2], af[i][3], addr);
            }
            #pragma unroll
            for (int jj = 0; jj < 2; jj++) {
                int kr = ks * 16 + b_kr;
                int cc = 4 * wn + 2 * jj + b_chi;
                uint32_t addr = sb + (uint32_t)(8192 + kr * 256 +
                                                ((cc ^ (kr & 7)) << 4));
                LDSM_X4T(bf[2 * jj][0], bf[2 * jj][1], bf[2 * jj + 1][0],
                         bf[2 * jj + 1][1], addr);
            }
            #pragma unroll
            for (int i = 0; i < 4; i++)
                #pragma unroll
                for (int j = 0; j < 4; j++) mma_f16(c[i][j], af[i], bf[j]);
        }

        if (ch < 29) ISSUE((ch + 3) & 3, (ch + 3) * 32);
    }

    int b = m0 >> 10;
    #pragma unroll
    for (int i = 0; i < 4; i++) {
        int row = m0 + wm * 64 + i * 16 + (lane >> 2);
        #pragma unroll
        for (int j = 0; j < 4; j++) {
            int col = n0 + wn * 32 + j * 8 + (lane & 3) * 2;
            float bb0 = bias[col], bb1 = bias[col + 1];
            if (ak) {
                bb0 += ak[b * HID_ + col];
                bb1 += ak[b * HID_ + col + 1];
            }
            *(float2*)(C + (size_t)row * 1024 + col) =
                make_float2(c[i][j][0] + bb0, c[i][j][1] + bb1);
            *(float2*)(C + (size_t)(row + 8) * 1024 + col) =
                make_float2(c[i][j][2] + bb0, c[i][j][3] + bb1);
        }
    }
}

// ===========================================================================
// fp16 flash attention (R11 structure; O now written as half for O-proj)
// ===========================================================================
#define ATTN_SMEM (32768 + 512)

__global__ __launch_bounds__(256) void attn_mma_kernel(
    const float* __restrict__ Q, const float* __restrict__ K,
    const float* __restrict__ V, const unsigned char* __restrict__ mask,
    __half* __restrict__ O) {
    extern __shared__ float sm[];
    uint32_t base = smem_to_u32(sm);
    uint32_t Kf = base;
    uint32_t Vf = base + 16384;
    float* Msf = sm + 32768 / 4;

    int tid = threadIdx.x;
    int lane = tid & 31, w = tid >> 5;
    int l2 = (lane >> 2) & 1;
    int l34 = lane >> 3, l3 = l34 & 1, l4 = (l34 >> 1) & 1;
    int r = lane >> 2, cl = lane & 3;
    int qt = blockIdx.x, h = blockIdx.y, b = blockIdx.z;

    const float* Qg = Q + ((size_t)(b * N_ + qt * 128) * HID_ + h * HD_);
    const float* Kg = K + ((size_t)b * N_ * HID_ + h * HD_);
    const float* Vg = V + ((size_t)b * N_ * HID_ + h * HD_);

    uint32_t qh[4][4];
    {
        const float sc = 0.125f;
        int m = 16 * w + r;
        #pragma unroll
        for (int ks = 0; ks < 4; ks++) {
            float2 v0 = *(const float2*)(Qg + (size_t)m * HID_ + 16 * ks + 2 * cl);
            float2 v1 = *(const float2*)(Qg + (size_t)(m + 8) * HID_ + 16 * ks + 2 * cl);
            float2 v2 = *(const float2*)(Qg + (size_t)m * HID_ + 16 * ks + 8 + 2 * cl);
            float2 v3 = *(const float2*)(Qg + (size_t)(m + 8) * HID_ + 16 * ks + 8 + 2 * cl);
            qh[ks][0] = h2(v0.x * sc, v0.y * sc);
            qh[ks][1] = h2(v1.x * sc, v1.y * sc);
            qh[ks][2] = h2(v2.x * sc, v2.y * sc);
            qh[ks][3] = h2(v3.x * sc, v3.y * sc);
        }
    }

    int kvK = 8 * w + (lane & 7);
    int vkap[2], vdq = l34 + 4 * (w >> 1);
    vkap[0] = (lane & 7) + 16 * (w & 1);
    vkap[1] = (lane & 7) + 8 + 16 * (w & 1);

    float4 kR[4], vA[2], vB[2];

    #define AT_LDG(t)                                                          \
        do {                                                                   \
            const float* kp = Kg + (size_t)((t) * 64 + kvK) * HID_;            \
            _Pragma("unroll")                                                  \
            for (int it = 0; it < 4; it++)                                     \
                kR[it] = *(const float4*)(kp + 4 * l34 + 16 * it);             \
            _Pragma("unroll")                                                  \
            for (int itv = 0; itv < 2; itv++) {                                \
                const float* vp = Vg + (size_t)((t) * 64 + 2 * vkap[itv]) *    \
                                  HID_ + 4 * vdq;                              \
                vA[itv] = *(const float4*)vp;                                  \
                vB[itv] = *(const float4*)(vp + HID_);                         \
            }                                                                  \
        } while (0)

    #define AT_STS(buf, t)                                                     \
        do {                                                                   \
            uint32_t Kb = Kf + (buf) * 8192;                                   \
            uint32_t Vb = Vf + (buf) * 8192;                                   \
            _Pragma("unroll")                                                  \
            for (int it = 0; it < 4; it++) {                                   \
                uint32_t tile = (uint32_t)(it * 8 + w);                        \
                uint32_t lane_hi = (uint32_t)(((lane & 7) << 2) | (l3 << 1));  \
                uint32_t ba = Kb + tile * 256 + (uint32_t)l4 * 4;              \
                uint32_t p0 = h2(kR[it].x, kR[it].y);                          \
                uint32_t p1 = h2(kR[it].z, kR[it].w);                          \
                STS32(ba + ((lane_hi | (uint32_t)l2) << 3), l2 ? p1 : p0);     \
                STS32(ba + ((lane_hi | (uint32_t)(1 - l2)) << 3), l2 ? p0 : p1); \
            }                                                                  \
            _Pragma("unroll")                                                  \
            for (int itv = 0; itv < 2; itv++) {                                \
                uint32_t ks2 = (uint32_t)(itv + 2 * (w & 1));                  \
                uint32_t tile = ks2 * 8 + (uint32_t)(l4 + 2 * (w >> 1));       \
                int rot = l34 & 3;                                             \
                float4 c0 = rot4(vA[itv], rot);                                \
                float4 c1 = rot4(vB[itv], rot);                                \
                uint32_t bb = Vb + tile * 256 + (uint32_t)l3 * 128 +           \
                              (uint32_t)(lane & 3) * 8 + (uint32_t)l2 * 4;     \
                STS32(bb + (uint32_t)(((rot + 0) & 3) << 5), h2(c0.x, c1.x));  \
                STS32(bb + (uint32_t)(((rot + 1) & 3) << 5), h2(c0.y, c1.y));  \
                STS32(bb + (uint32_t)(((rot + 2) & 3) << 5), h2(c0.z, c1.z));  \
                STS32(bb + (uint32_t)(((rot + 3) & 3) << 5), h2(c0.w, c1.w));  \
            }                                                                  \
            if (tid < 64)                                                      \
                Msf[(buf) * 64 + tid] =                                        \
                    mask[b * N_ + (t) * 64 + tid] ? 0.f : 1.f;                 \
        } while (0)

    float oacc[8][4];
    #pragma unroll
    for (int nf = 0; nf < 8; nf++)
        #pragma unroll
        for (int x = 0; x < 4; x++) oacc[nf][x] = 0.f;
    float sum0 = 0.f, sum1 = 0.f;

    AT_LDG(0);
    AT_STS(0, 0);
    __syncthreads();

    for (int t = 0; t < 16; t++) {
        int buf = t & 1;
        if (t < 15) AT_LDG(t + 1);

        uint32_t Kb = Kf + buf * 8192;
        uint32_t Vb = Vf + buf * 8192;

        float sacc[8][4];
        #pragma unroll
        for (int nf = 0; nf < 8; nf++)
            #pragma unroll
            for (int x = 0; x < 4; x++) sacc[nf][x] = 0.f;
        #pragma unroll
        for (int ks = 0; ks < 4; ks++) {
            #pragma unroll
            for (int nf = 0; nf < 8; nf++) {
                uint32_t bf[2];
                LDS64(Kb + (uint32_t)(ks * 8 + nf) * 256 + (uint32_t)lane * 8,
                      bf[0], bf[1]);
                mma_f16(sacc[nf], qh[ks], bf);
            }
        }

        uint32_t ph[8][2];
        const float* Mb = Msf + buf * 64;
        #pragma unroll
        for (int nf = 0; nf < 8; nf++) {
            float mm0 = Mb[nf * 8 + 2 * cl];
            float mm1 = Mb[nf * 8 + 2 * cl + 1];
            float p0 = fexp(sacc[nf][0]) * mm0;
            float p1 = fexp(sacc[nf][1]) * mm1;
            float p2 = fexp(sacc[nf][2]) * mm0;
            float p3 = fexp(sacc[nf][3]) * mm1;
            sum0 += p0 + p1;
            sum1 += p2 + p3;
            ph[nf][0] = h2(p0, p1);
            ph[nf][1] = h2(p2, p3);
        }

        #pragma unroll
        for (int ks2 = 0; ks2 < 4; ks2++) {
            uint32_t a[4] = {ph[2 * ks2][0], ph[2 * ks2][1],
                             ph[2 * ks2 + 1][0], ph[2 * ks2 + 1][1]};
            #pragma unroll
            for (int nf = 0; nf < 8; nf++) {
                uint32_t vf[2];
                LDS64(Vb + (uint32_t)(ks2 * 8 + nf) * 256 + (uint32_t)lane * 8,
                      vf[0], vf[1]);
                mma_f16(oacc[nf], a, vf);
            }
        }

        if (t < 15) {
            __syncthreads();
            AT_STS(buf ^ 1, t + 1);
            __syncthreads();
        }
    }

    sum0 += __shfl_xor_sync(0xffffffffu, sum0, 1);
    sum0 += __shfl_xor_sync(0xffffffffu, sum0, 2);
    sum1 += __shfl_xor_sync(0xffffffffu, sum1, 1);
    sum1 += __shfl_xor_sync(0xffffffffu, sum1, 2);
    float inv0 = 1.f / sum0, inv1 = 1.f / sum1;

    int row0 = b * N_ + qt * 128 + 16 * w + r;
    #pragma unroll
    for (int nf = 0; nf < 8; nf++) {
        int col = h * HD_ + nf * 8 + 2 * cl;
        *(uint32_t*)(O + (size_t)row0 * HID_ + col) =
            h2(oacc[nf][0] * inv0, oacc[nf][1] * inv0);
        *(uint32_t*)(O + (size_t)(row0 + 8) * HID_ + col) =
            h2(oacc[nf][2] * inv1, oacc[nf][3] * inv1);
    }
}

// ===========================================================================
extern "C" void kernel_launch(void* const* d_in, const int* in_sizes, int n_in,
                              void* d_out, int out_size) {
    const float* x = (const float*)d_in[0];
    const int* ct = (const int*)d_in[1];
    const float* gc = (const float*)d_in[2];
    const unsigned char* mask = (const unsigned char*)d_in[3];
    const float* Wq = (const float*)d_in[4];
    const float* bq = (const float*)d_in[5];
    const float* Wk = (const float*)d_in[6];
    const float* bk = (const float*)d_in[7];
    const float* Wv = (const float*)d_in[8];
    const float* bv = (const float*)d_in[9];
    const float* Wo = (const float*)d_in[10];
    const float* bo = (const float*)d_in[11];
    // d_in[12] ct_bias_emb, d_in[14..17] Wg1/bg1/Wg2/bg2 cancel in softmax
    const float* ct_key = (const float*)d_in[13];
    const float* Wgk = (const float*)d_in[18];
    const float* bgk = (const float*)d_in[19];

    float *Qb, *Kb, *Vb, *addk;
    __half *Oh, *xh, *Wqh, *Wkh, *Wvh, *Woh;
    cudaGetSymbolAddress((void**)&Qb, g_Q);
    cudaGetSymbolAddress((void**)&Kb, g_K);
    cudaGetSymbolAddress((void**)&Vb, g_V);
    cudaGetSymbolAddress((void**)&Oh, g_Oh);
    cudaGetSymbolAddress((void**)&xh, g_xh);
    cudaGetSymbolAddress((void**)&Wqh, g_Wqh);
    cudaGetSymbolAddress((void**)&Wkh, g_Wkh);
    cudaGetSymbolAddress((void**)&Wvh, g_Wvh);
    cudaGetSymbolAddress((void**)&Woh, g_Woh);
    cudaGetSymbolAddress((void**)&addk, g_addk);

    cudaFuncSetAttribute(gemm3h_kernel, cudaFuncAttributeMaxDynamicSharedMemorySize,
                         GEMM_SMEM);
    cudaFuncSetAttribute(attn_mma_kernel, cudaFuncAttributeMaxDynamicSharedMemorySize,
                         ATTN_SMEM);

    // fp32 -> fp16 conversions
    const int WN4 = HID_ * HID_ / 4, XN4 = B_ * N_ * HID_ / 4;
    f2h_kernel<<<XN4 / 256, 256>>>(x, xh, XN4);
    f2h_kernel<<<WN4 / 256, 256>>>(Wq, Wqh, WN4);
    f2h_kernel<<<WN4 / 256, 256>>>(Wk, Wkh, WN4);
    f2h_kernel<<<WN4 / 256, 256>>>(Wv, Wvh, WN4);
    f2h_kernel<<<WN4 / 256, 256>>>(Wo, Woh, WN4);

    prep_addk_kernel<<<B_, GDIM_>>>(ct, gc, Wgk, bgk, ct_key);

    // Fused Q/K/V projections (z selects weight/bias/output; addk -> K).
    dim3 qkvgrid(HID_ / 128, (B_ * N_) / 128, 3);  // (8, 64, 3)
    gemm3h_kernel<<<qkvgrid, 256, GEMM_SMEM>>>(
        xh, Wqh, Wkh, Wvh, bq, bk, bv, addk, Qb, Kb, Vb);

    dim3 agrid(N_ / 128, HEADS_, B_);  // (8, 16, 8)
    attn_mma_kernel<<<agrid, 256, ATTN_SMEM>>>(Qb, Kb, Vb, mask, Oh);

    dim3 ogrid(HID_ / 128, (B_ * N_) / 128, 1);
    gemm3h_kernel<<<ogrid, 256, GEMM_SMEM>>>(
        Oh, Woh, Woh, Woh, bo, bo, bo, nullptr, (float*)d_out, nullptr, nullptr);
}

// round 13
// speedup vs baseline: 2.5652x; 1.2734x over previous
#include <cuda_runtime.h>
#include <cuda_fp16.h>
#include <math.h>
#include <cstdint>

#define B_ 8
#define N_ 1024
#define HID_ 1024
#define HEADS_ 16
#define HD_ 64
#define GDIM_ 128

// Scratch (allocation-free rule: __device__ globals)
__device__ __half g_Qh[B_ * N_ * HID_];
__device__ __half g_Kh[B_ * N_ * HID_];
__device__ __half g_Vh[B_ * N_ * HID_];
__device__ __half g_Oh[B_ * N_ * HID_];
__device__ __half g_xh[B_ * N_ * HID_];
__device__ __half g_Wqh[HID_ * HID_];
__device__ __half g_Wkh[HID_ * HID_];
__device__ __half g_Wvh[HID_ * HID_];
__device__ __half g_Woh[HID_ * HID_];
__device__ float g_addk[B_ * HID_];

__device__ __forceinline__ uint32_t smem_to_u32(const void* p) {
    uint32_t a;
    asm("{ .reg .u64 t; cvta.to.shared.u64 t, %1; cvt.u32.u64 %0, t; }"
        : "=r"(a) : "l"(p));
    return a;
}
__device__ __forceinline__ uint32_t h2(float lo, float hi) {
    __half2 h = __floats2half2_rn(lo, hi);
    return *reinterpret_cast<uint32_t*>(&h);
}
__device__ __forceinline__ void mma_f16(float c[4], const uint32_t a[4],
                                        const uint32_t b[2]) {
    asm volatile(
        "mma.sync.aligned.m16n8k16.row.col.f32.f16.f16.f32 "
        "{%0,%1,%2,%3}, {%4,%5,%6,%7}, {%8,%9}, {%0,%1,%2,%3};"
        : "+f"(c[0]), "+f"(c[1]), "+f"(c[2]), "+f"(c[3])
        : "r"(a[0]), "r"(a[1]), "r"(a[2]), "r"(a[3]), "r"(b[0]), "r"(b[1]));
}
#define LDSM_X4(r0, r1, r2, r3, addr) \
    asm volatile("ldmatrix.sync.aligned.m8n8.x4.shared.b16 {%0,%1,%2,%3}, [%4];" \
        : "=r"(r0), "=r"(r1), "=r"(r2), "=r"(r3) : "r"(addr))
#define LDSM_X4T(r0, r1, r2, r3, addr) \
    asm volatile("ldmatrix.sync.aligned.m8n8.x4.trans.shared.b16 {%0,%1,%2,%3}, [%4];" \
        : "=r"(r0), "=r"(r1), "=r"(r2), "=r"(r3) : "r"(addr))
#define CP_ASYNC16(dst, src) \
    asm volatile("cp.async.cg.shared.global [%0], [%1], 16;" \
        :: "r"(dst), "l"(src) : "memory")
#define CP_COMMIT() asm volatile("cp.async.commit_group;" ::: "memory")
#define CP_WAIT2() asm volatile("cp.async.wait_group 2;" ::: "memory")
#define CP_WAIT1() asm volatile("cp.async.wait_group 1;" ::: "memory")

// FFMA-pipe exp (deg-5 exp2 poly, rel err ~2e-6). No MUFU.
__device__ __forceinline__ float fexp(float s) {
    float x = s * 1.4426950408889634f;
    int n = __float2int_rn(x);
    float f = x - (float)n;
    float p = 1.3333558146e-3f;
    p = fmaf(p, f, 9.6181291076e-3f);
    p = fmaf(p, f, 5.5504108664e-2f);
    p = fmaf(p, f, 2.4022650696e-1f);
    p = fmaf(p, f, 6.9314718056e-1f);
    p = fmaf(p, f, 1.0f);
    n = max(-126, min(127, n));
    float sc = __int_as_float((uint32_t)(n + 127) << 23);
    return p * sc;
}

// ===========================================================================
// fp32 -> fp16 conversion (over float4)
// ===========================================================================
__global__ void f2h_kernel(const float* __restrict__ s, __half* __restrict__ d,
                           int n4) {
    int i = blockIdx.x * blockDim.x + threadIdx.x;
    if (i < n4) {
        float4 v = ((const float4*)s)[i];
        uint2 o;
        o.x = h2(v.x, v.y);
        o.y = h2(v.z, v.w);
        ((uint2*)d)[i] = o;
    }
}

// ===========================================================================
// Prep: addk[b][c] = elu(gc[b] @ Wgk + bgk)[c] + ct_key_emb[ct[b]][c]
// ===========================================================================
__global__ void prep_addk_kernel(const int* __restrict__ ct,
                                 const float* __restrict__ gc,
                                 const float* __restrict__ Wgk,
                                 const float* __restrict__ bgk,
                                 const float* __restrict__ ct_key_emb) {
    int b = blockIdx.x;
    int tid = threadIdx.x;
    __shared__ float g[GDIM_];
    g[tid] = gc[b * GDIM_ + tid];
    __syncthreads();
    int ctb = ct[b];
    for (int c = tid; c < HID_; c += GDIM_) {
        float s = bgk[c];
        #pragma unroll 8
        for (int i = 0; i < GDIM_; i++) s = fmaf(g[i], Wgk[i * HID_ + c], s);
        float e = (s > 0.f) ? s : (expf(s) - 1.f);
        g_addk[b * HID_ + c] = e + ct_key_emb[ctb * HID_ + c];
    }
}

// ===========================================================================
// fp16 cp.async + ldmatrix GEMM. Half outputs (H*) for QKV (Q scaled 1/8),
// float output (C*) for O-proj.
// ===========================================================================
#define GEMM_SMEM 65536

__global__ __launch_bounds__(256, 2) void gemm3h_kernel(
    const __half* __restrict__ A,
    const __half* __restrict__ W0, const __half* __restrict__ W1,
    const __half* __restrict__ W2,
    const float* __restrict__ bi0, const float* __restrict__ bi1,
    const float* __restrict__ bi2,
    const float* __restrict__ addk,
    float* __restrict__ C0,
    __half* __restrict__ H0, __half* __restrict__ H1, __half* __restrict__ H2) {
    extern __shared__ float sm[];
    uint32_t sbase = smem_to_u32(sm);

    int z = blockIdx.z;
    const __half* W = (z == 0) ? W0 : ((z == 1) ? W1 : W2);
    const float* bias = (z == 0) ? bi0 : ((z == 1) ? bi1 : bi2);
    __half* Ch = (z == 0) ? H0 : ((z == 1) ? H1 : H2);
    const float* ak = (z == 1) ? addk : nullptr;

    int tid = threadIdx.x;
    int lane = tid & 31, w = tid >> 5;
    int wm = w >> 2, wn = w & 3;
    int m0 = blockIdx.y * 128, n0 = blockIdx.x * 128;

    int arow0 = tid >> 2, ac = tid & 3;
    uint32_t asm0 = (uint32_t)(arow0 * 64 + ((ac ^ ((arow0 >> 1) & 3)) << 4));
    int arow1 = arow0 + 64;
    uint32_t asm1 = (uint32_t)(arow1 * 64 + ((ac ^ ((arow1 >> 1) & 3)) << 4));
    int bkr0 = tid >> 4, bc = tid & 15;
    uint32_t bsm0 = (uint32_t)(bkr0 * 256 + ((bc ^ (bkr0 & 7)) << 4) + 8192);
    int bkr1 = bkr0 + 16;
    uint32_t bsm1 = (uint32_t)(bkr1 * 256 + ((bc ^ (bkr1 & 7)) << 4) + 8192);

    #define ISSUE(stage, k0)                                                   \
        do {                                                                   \
            uint32_t sb = sbase + (uint32_t)(stage) * 16384;                   \
            CP_ASYNC16(sb + asm0,                                              \
                       A + (size_t)(m0 + arow0) * 1024 + (k0) + ac * 8);       \
            CP_ASYNC16(sb + asm1,                                              \
                       A + (size_t)(m0 + arow1) * 1024 + (k0) + ac * 8);       \
            CP_ASYNC16(sb + bsm0,                                              \
                       W + (size_t)((k0) + bkr0) * 1024 + n0 + bc * 8);        \
            CP_ASYNC16(sb + bsm1,                                              \
                       W + (size_t)((k0) + bkr1) * 1024 + n0 + bc * 8);        \
            CP_COMMIT();                                                       \
        } while (0)

    int a_row = wm * 64 + (lane & 15);
    int a_swz = ((lane & 15) >> 1) & 3;
    int b_kr = (lane & 7) + 8 * ((lane >> 3) & 1);
    int b_chi = lane >> 4;

    float c[4][4][4];
    #pragma unroll
    for (int i = 0; i < 4; i++)
        #pragma unroll
        for (int j = 0; j < 4; j++)
            #pragma unroll
            for (int r = 0; r < 4; r++) c[i][j][r] = 0.f;

    ISSUE(0, 0);
    ISSUE(1, 32);
    ISSUE(2, 64);

    for (int ch = 0; ch < 32; ch++) {
        CP_WAIT2();
        __syncthreads();
        uint32_t sb = sbase + (uint32_t)(ch & 3) * 16384;

        #pragma unroll
        for (int ks = 0; ks < 2; ks++) {
            uint32_t af[4][4], bf[4][2];
            #pragma unroll
            for (int i = 0; i < 4; i++) {
                int row = a_row + 16 * i;
                int cc = 2 * ks + b_chi;
                uint32_t addr = sb + (uint32_t)(row * 64 + ((cc ^ a_swz) << 4));
                LDSM_X4(af[i][0], af[i][1], af[i][2], af[i][3], addr);
            }
            #pragma unroll
            for (int jj = 0; jj < 2; jj++) {
                int kr = ks * 16 + b_kr;
                int cc = 4 * wn + 2 * jj + b_chi;
                uint32_t addr = sb + (uint32_t)(8192 + kr * 256 +
                                                ((cc ^ (kr & 7)) << 4));
                LDSM_X4T(bf[2 * jj][0], bf[2 * jj][1], bf[2 * jj + 1][0],
                         bf[2 * jj + 1][1], addr);
            }
            #pragma unroll
            for (int i = 0; i < 4; i++)
                #pragma unroll
                for (int j = 0; j < 4; j++) mma_f16(c[i][j], af[i], bf[j]);
        }

        if (ch < 29) ISSUE((ch + 3) & 3, (ch + 3) * 32);
        else CP_COMMIT();  // keep group-count invariant for wait_group 2
    }

    int b = m0 >> 10;
    float qsc = (Ch && z == 0) ? 0.125f : 1.0f;
    #pragma unroll
    for (int i = 0; i < 4; i++) {
        int row = m0 + wm * 64 + i * 16 + (lane >> 2);
        #pragma unroll
        for (int j = 0; j < 4; j++) {
            int col = n0 + wn * 32 + j * 8 + (lane & 3) * 2;
            float bb0 = bias[col], bb1 = bias[col + 1];
            if (ak) {
                bb0 += ak[b * HID_ + col];
                bb1 += ak[b * HID_ + col + 1];
            }
            float v00 = (c[i][j][0] + bb0) * qsc, v01 = (c[i][j][1] + bb1) * qsc;
            float v10 = (c[i][j][2] + bb0) * qsc, v11 = (c[i][j][3] + bb1) * qsc;
            if (Ch) {
                *(uint32_t*)(Ch + (size_t)row * 1024 + col) = h2(v00, v01);
                *(uint32_t*)(Ch + (size_t)(row + 8) * 1024 + col) = h2(v10, v11);
            } else {
                *(float2*)(C0 + (size_t)row * 1024 + col) = make_float2(v00, v01);
                *(float2*)(C0 + (size_t)(row + 8) * 1024 + col) =
                    make_float2(v10, v11);
            }
        }
    }
}

// ===========================================================================
// fp16 flash attention: cp.async 3-stage K/V pipeline + ldmatrix fragments.
// CTA = 128 q-rows x head. smem: Q 16KB @0, stages 16KB each @16384 (K 8KB +
// V 8KB), mask 3x64 floats @65536. Total 66304 B.
// K (row-major [kv][d]) -> non-trans ldmatrix = B frag for S=QK^T.
// V (row-major [kv][d]) -> trans ldmatrix = B frag for O=PV.
// ===========================================================================
#define ATTN_SMEM (65536 + 768)

__global__ __launch_bounds__(256) void attn_mma_kernel(
    const __half* __restrict__ Q, const __half* __restrict__ K,
    const __half* __restrict__ V, const unsigned char* __restrict__ mask,
    __half* __restrict__ O) {
    extern __shared__ float sm[];
    uint32_t base = smem_to_u32(sm);
    uint32_t Qs = base;
    uint32_t KV0 = base + 16384;
    float* Msf = sm + 65536 / 4;

    int tid = threadIdx.x;
    int lane = tid & 31, w = tid >> 5;
    int r = lane >> 2, cl = lane & 3;
    int qt = blockIdx.x, h = blockIdx.y, b = blockIdx.z;

    const __half* Qg = Q + ((size_t)(b * N_ + qt * 128) * HID_ + h * HD_);
    const __half* Kg = K + ((size_t)b * N_ * HID_ + h * HD_);
    const __half* Vg = V + ((size_t)b * N_ * HID_ + h * HD_);

    // Q tile: 128 rows x 128B, swizzle chunk c^(row&7)
    #pragma unroll
    for (int it = 0; it < 4; it++) {
        int s = tid + it * 256;
        int row = s >> 3, cc = s & 7;
        CP_ASYNC16(Qs + (uint32_t)(row * 128 + ((cc ^ (row & 7)) << 4)),
                   Qg + (size_t)row * HID_ + cc * 8);
    }
    CP_COMMIT();

    #define AT_ISSUE(t)                                                        \
        do {                                                                   \
            uint32_t sb = KV0 + (uint32_t)((t) % 3) * 16384;                   \
            const __half* kp = Kg + (size_t)(t) * 64 * HID_;                   \
            const __half* vp = Vg + (size_t)(t) * 64 * HID_;                   \
            _Pragma("unroll")                                                  \
            for (int it = 0; it < 2; it++) {                                   \
                int s = tid + it * 256;                                        \
                int row = s >> 3, cc = s & 7;                                  \
                uint32_t d =                                                   \
                    sb + (uint32_t)(row * 128 + ((cc ^ (row & 7)) << 4));      \
                const __half* off = kp + (size_t)row * HID_ + cc * 8;          \
                CP_ASYNC16(d, off);                                            \
                CP_ASYNC16(d + 8192, vp + (size_t)row * HID_ + cc * 8);        \
            }                                                                  \
            CP_COMMIT();                                                       \
        } while (0)

    #define AT_MASK(t)                                                         \
        do {                                                                   \
            if (tid < 64)                                                      \
                Msf[((t) % 3) * 64 + tid] =                                    \
                    mask[b * N_ + (t) * 64 + tid] ? 0.f : 1.f;                 \
        } while (0)

    AT_ISSUE(0);
    AT_MASK(0);
    AT_ISSUE(1);
    AT_MASK(1);

    uint32_t qh[4][4];
    float oacc[8][4];
    #pragma unroll
    for (int nf = 0; nf < 8; nf++)
        #pragma unroll
        for (int x = 0; x < 4; x++) oacc[nf][x] = 0.f;
    float sum0 = 0.f, sum1 = 0.f;

    for (int t = 0; t < 16; t++) {
        CP_WAIT1();
        __syncthreads();

        if (t == 0) {
            // Q fragments (A operand), Q already scaled by 1/8 in projection
            int row = 16 * w + (lane & 15);
            #pragma unroll
            for (int ks = 0; ks < 4; ks++) {
                int cc = 2 * ks + (lane >> 4);
                uint32_t addr =
                    Qs + (uint32_t)(row * 128 + ((cc ^ (row & 7)) << 4));
                LDSM_X4(qh[ks][0], qh[ks][1], qh[ks][2], qh[ks][3], addr);
            }
        }

        uint32_t Kb = KV0 + (uint32_t)(t % 3) * 16384;
        uint32_t Vb = Kb + 8192;

        // S = Q K^T
        float sacc[8][4];
        #pragma unroll
        for (int nf = 0; nf < 8; nf++)
            #pragma unroll
            for (int x = 0; x < 4; x++) sacc[nf][x] = 0.f;
        int mi = lane >> 3, r8 = lane & 7;
        #pragma unroll
        for (int ks = 0; ks < 4; ks++) {
            #pragma unroll
            for (int p = 0; p < 4; p++) {
                int row = (2 * p + (mi >> 1)) * 8 + r8;
                int cc = 2 * ks + (mi & 1);
                uint32_t addr = Kb + (uint32_t)(row * 128 + ((cc ^ r8) << 4));
                uint32_t b0, b1, b2, b3;
                LDSM_X4(b0, b1, b2, b3, addr);
                uint32_t bf0[2] = {b0, b1}, bf1[2] = {b2, b3};
                mma_f16(sacc[2 * p], qh[ks], bf0);
                mma_f16(sacc[2 * p + 1], qh[ks], bf1);
            }
        }

        // exp + mask; P stays in registers (S-accum layout == A-frag layout)
        uint32_t ph[8][2];
        const float* Mb = Msf + (t % 3) * 64;
        #pragma unroll
        for (int nf = 0; nf < 8; nf++) {
            float mm0 = Mb[nf * 8 + 2 * cl];
            float mm1 = Mb[nf * 8 + 2 * cl + 1];
            float p0 = fexp(sacc[nf][0]) * mm0;
            float p1 = fexp(sacc[nf][1]) * mm1;
            float p2 = fexp(sacc[nf][2]) * mm0;
            float p3 = fexp(sacc[nf][3]) * mm1;
            sum0 += p0 + p1;
            sum1 += p2 + p3;
            ph[nf][0] = h2(p0, p1);
            ph[nf][1] = h2(p2, p3);
        }

        // O += P V
        int kr_lo = (lane & 7) + 8 * ((lane >> 3) & 1);
        int chi = lane >> 4;
        #pragma unroll
        for (int ks2 = 0; ks2 < 4; ks2++) {
            uint32_t a[4] = {ph[2 * ks2][0], ph[2 * ks2][1],
                             ph[2 * ks2 + 1][0], ph[2 * ks2 + 1][1]};
            #pragma unroll
            for (int p = 0; p < 4; p++) {
                int kr = ks2 * 16 + kr_lo;
                int cc = 2 * p + chi;
                uint32_t addr =
                    Vb + (uint32_t)(kr * 128 + ((cc ^ (kr & 7)) << 4));
                uint32_t v0, v1, v2, v3;
                LDSM_X4T(v0, v1, v2, v3, addr);
                uint32_t vf0[2] = {v0, v1}, vf1[2] = {v2, v3};
                mma_f16(oacc[2 * p], a, vf0);
                mma_f16(oacc[2 * p + 1], a, vf1);
            }
        }

        if (t < 14) {
            AT_ISSUE(t + 2);
            AT_MASK(t + 2);
        } else {
            CP_COMMIT();  // keep group-count invariant for wait_group 1
        }
    }

    sum0 += __shfl_xor_sync(0xffffffffu, sum0, 1);
    sum0 += __shfl_xor_sync(0xffffffffu, sum0, 2);
    sum1 += __shfl_xor_sync(0xffffffffu, sum1, 1);
    sum1 += __shfl_xor_sync(0xffffffffu, sum1, 2);
    float inv0 = 1.f / sum0, inv1 = 1.f / sum1;

    int row0 = b * N_ + qt * 128 + 16 * w + r;
    #pragma unroll
    for (int nf = 0; nf < 8; nf++) {
        int col = h * HD_ + nf * 8 + 2 * cl;
        *(uint32_t*)(O + (size_t)row0 * HID_ + col) =
            h2(oacc[nf][0] * inv0, oacc[nf][1] * inv0);
        *(uint32_t*)(O + (size_t)(row0 + 8) * HID_ + col) =
            h2(oacc[nf][2] * inv1, oacc[nf][3] * inv1);
    }
}

// ===========================================================================
extern "C" void kernel_launch(void* const* d_in, const int* in_sizes, int n_in,
                              void* d_out, int out_size) {
    const float* x = (const float*)d_in[0];
    const int* ct = (const int*)d_in[1];
    const float* gc = (const float*)d_in[2];
    const unsigned char* mask = (const unsigned char*)d_in[3];
    const float* Wq = (const float*)d_in[4];
    const float* bq = (const float*)d_in[5];
    const float* Wk = (const float*)d_in[6];
    const float* bk = (const float*)d_in[7];
    const float* Wv = (const float*)d_in[8];
    const float* bv = (const float*)d_in[9];
    const float* Wo = (const float*)d_in[10];
    const float* bo = (const float*)d_in[11];
    // d_in[12] ct_bias_emb, d_in[14..17] Wg1/bg1/Wg2/bg2 cancel in softmax
    const float* ct_key = (const float*)d_in[13];
    const float* Wgk = (const float*)d_in[18];
    const float* bgk = (const float*)d_in[19];

    float* addk;
    __half *Qh, *Kh, *Vh, *Oh, *xh, *Wqh, *Wkh, *Wvh, *Woh;
    cudaGetSymbolAddress((void**)&Qh, g_Qh);
    cudaGetSymbolAddress((void**)&Kh, g_Kh);
    cudaGetSymbolAddress((void**)&Vh, g_Vh);
    cudaGetSymbolAddress((void**)&Oh, g_Oh);
    cudaGetSymbolAddress((void**)&xh, g_xh);
    cudaGetSymbolAddress((void**)&Wqh, g_Wqh);
    cudaGetSymbolAddress((void**)&Wkh, g_Wkh);
    cudaGetSymbolAddress((void**)&Wvh, g_Wvh);
    cudaGetSymbolAddress((void**)&Woh, g_Woh);
    cudaGetSymbolAddress((void**)&addk, g_addk);

    cudaFuncSetAttribute(gemm3h_kernel, cudaFuncAttributeMaxDynamicSharedMemorySize,
                         GEMM_SMEM);
    cudaFuncSetAttribute(attn_mma_kernel, cudaFuncAttributeMaxDynamicSharedMemorySize,
                         ATTN_SMEM);

    // fp32 -> fp16 conversions
    const int WN4 = HID_ * HID_ / 4, XN4 = B_ * N_ * HID_ / 4;
    f2h_kernel<<<XN4 / 256, 256>>>(x, xh, XN4);
    f2h_kernel<<<WN4 / 256, 256>>>(Wq, Wqh, WN4);
    f2h_kernel<<<WN4 / 256, 256>>>(Wk, Wkh, WN4);
    f2h_kernel<<<WN4 / 256, 256>>>(Wv, Wvh, WN4);
    f2h_kernel<<<WN4 / 256, 256>>>(Wo, Woh, WN4);

    prep_addk_kernel<<<B_, GDIM_>>>(ct, gc, Wgk, bgk, ct_key);

    // Fused Q/K/V projections -> fp16 outputs (Q scaled by 1/8, K gets addk)
    dim3 qkvgrid(HID_ / 128, (B_ * N_) / 128, 3);  // (8, 64, 3)
    gemm3h_kernel<<<qkvgrid, 256, GEMM_SMEM>>>(
        xh, Wqh, Wkh, Wvh, bq, bk, bv, addk, nullptr, Qh, Kh, Vh);

    dim3 agrid(N_ / 128, HEADS_, B_);  // (8, 16, 8)
    attn_mma_kernel<<<agrid, 256, ATTN_SMEM>>>(Qh, Kh, Vh, mask, Oh);

    dim3 ogrid(HID_ / 128, (B_ * N_) / 128, 1);
    gemm3h_kernel<<<ogrid, 256, GEMM_SMEM>>>(
        Oh, Woh, Woh, Woh, bo, bo, bo, nullptr, (float*)d_out,
        nullptr, nullptr, nullptr);
}